// round 11
// baseline (speedup 1.0000x reference)
#include <cuda_runtime.h>
#include <cuda_fp16.h>
#include <math.h>

#define NTOK 4096
#define HID  1024
#define ADIM 64
#define NCAT 8
#define MAXT 40
#define NBV  128
#define NSM  148

typedef unsigned int u32;
typedef unsigned long long u64;

// ---------------- scratch (static device globals; no allocation) -------------
__device__ int g_order[NTOK];
__device__ int g_tile_cat[MAXT];
__device__ int g_tile_row[MAXT];
__device__ int g_cat_base[NCAT];
__device__ int g_cat_count[NCAT];
__device__ int g_num_tiles;

__device__ __align__(16) __half g_ah[NTOK * ADIM];      // actions fp16
__device__ __align__(16) __half g_tauh[NBV * HID];      // tau_emb fp16 (128 rows)
__device__ __align__(16) __half g_x1h[NTOK * HID];      // a_emb fp16
__device__ __align__(16) __half g_h2h[NTOK * HID];      // hidden fp16
__device__ __align__(16) float  g_tau[NCAT * NBV * HID];// T[cat][t][n] fp32

// converted weights: [c][n][k] fp16 (k contiguous, full K rows)
#define W1OFF 0
#define W1SZ  (NCAT * HID * ADIM)
#define W2OFF (W1OFF + W1SZ)
#define W2SZ  (NCAT * HID * 2 * HID)
#define W3OFF (W2OFF + W2SZ)
#define W3SZ  (NCAT * HID * HID)
#define WTOT  (W3OFF + W3SZ)
__device__ __align__(16) __half g_Wh[WTOT];

// ---------------- helpers -----------------------------------------------------
__device__ __forceinline__ u32 smem_u32(const void* p) {
    u32 a;
    asm("{ .reg .u64 t; cvta.to.shared.u64 t, %1; cvt.u32.u64 %0, t; }"
        : "=r"(a) : "l"(p));
    return a;
}
__device__ __forceinline__ u32 hpack(__half a, __half b) {
    return ((u32)__half_as_ushort(b) << 16) | (u32)__half_as_ushort(a);
}
__device__ __forceinline__ u32 swz128(u32 o) { return o ^ ((o >> 3) & 0x70); }

__device__ __forceinline__ void cpasync16(u32 dst, const void* src, u32 srcsz) {
    asm volatile("cp.async.cg.shared.global [%0], [%1], 16, %2;"
                 :: "r"(dst), "l"(src), "r"(srcsz) : "memory");
}
__device__ __forceinline__ void cp_commit() {
    asm volatile("cp.async.commit_group;" ::: "memory");
}
__device__ __forceinline__ void cp_wait2() {
    asm volatile("cp.async.wait_group 2;" ::: "memory");
}
#define LDSM4(r, addr)                                                         \
    asm volatile("ldmatrix.sync.aligned.m8n8.x4.shared.b16 {%0,%1,%2,%3}, [%4];" \
                 : "=r"((r)[0]), "=r"((r)[1]), "=r"((r)[2]), "=r"((r)[3])      \
                 : "r"(addr))
#define MMA(d, a, b)                                                           \
    asm volatile("mma.sync.aligned.m16n8k16.row.col.f32.f16.f16.f32 "          \
                 "{%0,%1,%2,%3},{%4,%5,%6,%7},{%8,%9},{%0,%1,%2,%3};"          \
                 : "+f"((d)[0]), "+f"((d)[1]), "+f"((d)[2]), "+f"((d)[3])      \
                 : "r"((a)[0]), "r"((a)[1]), "r"((a)[2]), "r"((a)[3]),         \
                   "r"((b)[0]), "r"((b)[1]))

// ---------------- prep: ordering (block 0) + tauh + act cvt + tau zero --------
__global__ __launch_bounds__(256)
void k_prep(const int* __restrict__ cat_ids, const int* __restrict__ ts,
            const float* __restrict__ actions, int nb)
{
    int tid = threadIdx.x;
    if (blockIdx.x == 0) {
        __shared__ int thr_cnt[256 * NCAT];
        __shared__ int cat_tot[NCAT];
        __shared__ int cat_base_s[NCAT];
        int loc[NCAT];
        #pragma unroll
        for (int c = 0; c < NCAT; c++) loc[c] = 0;
        int i0 = tid * 16;
        #pragma unroll
        for (int j = 0; j < 16; j++) loc[cat_ids[i0 + j]]++;
        #pragma unroll
        for (int c = 0; c < NCAT; c++) thr_cnt[tid * NCAT + c] = loc[c];
        __syncthreads();
        if (tid < NCAT) {
            int run = 0;
            for (int i = 0; i < 256; i++) {
                int v = thr_cnt[i * NCAT + tid];
                thr_cnt[i * NCAT + tid] = run;
                run += v;
            }
            cat_tot[tid] = run;
        }
        __syncthreads();
        if (tid == 0) {
            int acc = 0, nt = 0;
            for (int c = 0; c < NCAT; c++) {
                g_cat_base[c]  = acc;
                g_cat_count[c] = cat_tot[c];
                cat_base_s[c]  = acc;
                for (int r = 0; r < cat_tot[c]; r += 128) {
                    g_tile_cat[nt] = c;
                    g_tile_row[nt] = acc + r;
                    nt++;
                }
                acc += cat_tot[c];
            }
            g_num_tiles = nt;
        }
        __syncthreads();
        int off[NCAT];
        #pragma unroll
        for (int c = 0; c < NCAT; c++)
            off[c] = cat_base_s[c] + thr_cnt[tid * NCAT + c];
        #pragma unroll
        for (int j = 0; j < 16; j++) {
            int cc = cat_ids[i0 + j];
            g_order[off[cc]++] = i0 + j;
        }
        return;
    }
    int gt = (blockIdx.x - 1) * 256 + tid;
    int stride = (gridDim.x - 1) * 256;
    const float kc = -9.210340371976184f / 512.0f;
    // tau_emb rows (zero beyond nb)
    for (int idx = gt; idx < NBV * HID; idx += stride) {
        int t = idx >> 10;
        int j = idx & (HID - 1);
        float v = 0.f;
        if (t < nb) {
            int m = j >> 1;
            float tv = (float)ts[t];
            float ang = tv * expf((float)m * kc);
            v = (j & 1) ? cosf(ang) : sinf(ang);
        }
        g_tauh[idx] = __float2half_rn(v);
    }
    // actions fp16
    for (int idx = gt; idx < NTOK * ADIM; idx += stride)
        g_ah[idx] = __float2half_rn(actions[idx]);
    // zero T table (accumulated by atomicAdd)
    for (int idx = gt; idx < NCAT * NBV * HID / 4; idx += stride)
        ((float4*)g_tau)[idx] = make_float4(0.f, 0.f, 0.f, 0.f);
}

// ------- weight convert + transpose, coalesced 128B stores --------------------
__global__ __launch_bounds__(256)
void k_wsplit(const float* __restrict__ W1, const float* __restrict__ W2,
              const float* __restrict__ W3)
{
    __shared__ float s[32][72];
    int ky = blockIdx.y;
    const float* src; size_t woff; int K, kt;
    if (ky < 1)       { src = W1; woff = W1OFF; K = ADIM;    kt = ky; }
    else if (ky < 33) { src = W2; woff = W2OFF; K = 2 * HID; kt = ky - 1; }
    else              { src = W3; woff = W3OFF; K = HID;     kt = ky - 33; }
    int n0 = blockIdx.x * 32, k0 = kt * 64, c = blockIdx.z;
    int tid = threadIdx.x;

    #pragma unroll
    for (int i = 0; i < 2; i++) {
        int idx = tid + i * 256;
        int kr = idx >> 3, n4 = (idx & 7) * 4;
        float4 v = *(const float4*)(src + ((size_t)c * K + k0 + kr) * HID + n0 + n4);
        s[n4 + 0][kr] = v.x;
        s[n4 + 1][kr] = v.y;
        s[n4 + 2][kr] = v.z;
        s[n4 + 3][kr] = v.w;
    }
    __syncthreads();

    int nr = tid >> 3, k8 = (tid & 7) * 8;
    u32 p[4];
    #pragma unroll
    for (int q = 0; q < 4; q++)
        p[q] = hpack(__float2half_rn(s[nr][k8 + 2 * q]),
                     __float2half_rn(s[nr][k8 + 2 * q + 1]));
    size_t di = woff + ((size_t)c * HID + n0 + nr) * (size_t)K + k0 + k8;
    *(uint4*)(g_Wh + di) = make_uint4(p[0], p[1], p[2], p[3]);
}

// ---------------- grouped HMMA GEMM, compacted one-wave scheduling ------------
// grid = 148 CTAs; each strides over compacted units (no hole CTAs).
// CTA 128x256, 8 warps (2x4), warp tile 64x64. K chunks of 64, 4-stage
// cp.async pipeline (wait_group 2, uniform commits across units).
#define A_OFF 0
#define B_OFF 16384
#define STG   49152
#define NSTG  4
#define SMEM_TOTAL (1024 + NSTG * STG)

template<int MODE>
__global__ __launch_bounds__(256, 1)
void k_gm(const float* __restrict__ bias_g, float* __restrict__ out_ext, int nb)
{
    extern __shared__ char smem[];
    int tid = threadIdx.x, lid = tid & 31, wid = tid >> 5;
    int wm = wid >> 2, wn = wid & 3;
    int* tok_s = (int*)smem;
    u32 st0 = smem_u32(smem) + 1024;

    int am = tid >> 3, ac = tid & 7;
    u32 dst0 = swz128(am * 128 + ac * 16);

    u32 aRow[4], bRow[4];
    #pragma unroll
    for (int mt = 0; mt < 4; mt++)
        aRow[mt] = (wm * 64 + mt * 16 + (lid & 15)) * 128;
    u32 aHs = (lid >> 4) * 16;
    #pragma unroll
    for (int nh = 0; nh < 4; nh++)
        bRow[nh] = (wn * 64 + nh * 16 + (lid & 7) + ((lid >> 4) << 3)) * 128;
    u32 bHs = ((lid >> 3) & 1) * 16;

    int ntl = g_num_tiles;
    int nu = (MODE == 0) ? 64 + 4 * ntl : 4 * ntl;

    for (int u = blockIdx.x; u < nu; u += NSM) {
        __syncthreads();   // prior unit fully retired before tok_s/stage reuse

        int cat, n0, nvalid, row0 = 0, K, ldin, ldw, koff;
        bool tauu = false;
        const __half* inp;
        size_t wb;
        if (MODE == 0 && u < 64) {
            tauu = true;
            int ks = u & 1;
            n0 = ((u >> 1) & 3) * 256;
            cat = u >> 3;
            K = 512; ldin = HID; ldw = 2 * HID; koff = HID + ks * 512;
            inp = g_tauh + ks * 512;
            wb = W2OFF;
            nvalid = 128;
        } else if (MODE == 0) {
            int v = u - 64;
            int tile = v >> 2;
            cat = g_tile_cat[tile]; row0 = g_tile_row[tile];
            n0 = (v & 3) * 256;
            K = ADIM; ldin = ADIM; ldw = ADIM; koff = 0;
            inp = g_ah; wb = W1OFF;
            nvalid = g_cat_base[cat] + g_cat_count[cat] - row0;
            if (nvalid > 128) nvalid = 128;
        } else {
            int tile = u >> 2;
            cat = g_tile_cat[tile]; row0 = g_tile_row[tile];
            n0 = (u & 3) * 256;
            K = HID; ldin = HID; koff = 0;
            if (MODE == 2) { ldw = 2 * HID; inp = g_x1h; wb = W2OFF; }
            else           { ldw = HID;     inp = g_h2h; wb = W3OFF; }
            nvalid = g_cat_base[cat] + g_cat_count[cat] - row0;
            if (nvalid > 128) nvalid = 128;
        }

        if (tid < 128)
            tok_s[tid] = (tid < nvalid) ? (tauu ? tid : g_order[row0 + tid]) : -1;
        __syncthreads();

        // ---- cp.async descriptors ----
        const __half* a_src[4];
        u32 a_sz[4];
        #pragma unroll
        for (int i = 0; i < 4; i++) {
            int tok = tok_s[am + 32 * i];
            int t2 = (tok < 0) ? 0 : tok;
            a_src[i] = inp + (size_t)t2 * ldin + ac * 8;
            a_sz[i] = (tok < 0) ? 0u : 16u;
        }
        const __half* b_src0 = g_Wh + wb +
                               ((size_t)cat * HID + n0 + am) * (size_t)ldw + koff + ac * 8;
        size_t b_stride = (size_t)32 * ldw;

        float acc[4][8][4];
        #pragma unroll
        for (int i = 0; i < 4; i++)
            #pragma unroll
            for (int j = 0; j < 8; j++)
                #pragma unroll
                for (int q = 0; q < 4; q++) acc[i][j][q] = 0.f;

        int nch = K / 64;

        auto issue = [&](int ch) {
            if (ch < nch) {
                int kg = ch * 64;
                u32 so = st0 + (ch & (NSTG - 1)) * STG;
                #pragma unroll
                for (int i = 0; i < 4; i++)
                    cpasync16(so + A_OFF + dst0 + i * 4096, a_src[i] + kg, a_sz[i]);
                #pragma unroll
                for (int i = 0; i < 8; i++)
                    cpasync16(so + B_OFF + dst0 + i * 4096, b_src0 + i * b_stride + kg, 16);
            }
            cp_commit();   // uniform commits keep wait_group counting valid
        };

        issue(0); issue(1); issue(2);

        for (int c = 0; c < nch; c++) {
            cp_wait2();
            __syncthreads();
            issue(c + 3);

            u32 so = st0 + (c & (NSTG - 1)) * STG;
            #pragma unroll
            for (int s = 0; s < 4; s++) {
                u32 ah[4][4], bh[4][4];
                #pragma unroll
                for (int mt = 0; mt < 4; mt++)
                    LDSM4(ah[mt], so + A_OFF + swz128(aRow[mt] + s * 32 + aHs));
                #pragma unroll
                for (int nh = 0; nh < 4; nh++)
                    LDSM4(bh[nh], so + B_OFF + swz128(bRow[nh] + s * 32 + bHs));
                #pragma unroll
                for (int mt = 0; mt < 4; mt++)
                    #pragma unroll
                    for (int nh = 0; nh < 4; nh++) {
                        MMA(acc[mt][nh * 2 + 0], ah[mt], bh[nh] + 0);
                        MMA(acc[mt][nh * 2 + 1], ah[mt], bh[nh] + 2);
                    }
            }
        }

        // ---- epilogue ----
        int g4 = lid >> 2, t4 = lid & 3;

        #pragma unroll
        for (int mt = 0; mt < 4; mt++) {
            int r0 = wm * 64 + mt * 16 + g4;
            int tok0 = tok_s[r0], tok1 = tok_s[r0 + 8];
            const float *T0 = 0, *T1 = 0;
            if (MODE == 2) {
                if (tok0 >= 0)
                    T0 = g_tau + ((size_t)cat * NBV + (tok0 % nb)) * HID + n0;
                if (tok1 >= 0)
                    T1 = g_tau + ((size_t)cat * NBV + (tok1 % nb)) * HID + n0;
            }
            #pragma unroll
            for (int j = 0; j < 8; j++) {
                int col = wn * 64 + j * 8 + t4 * 2;
                float bb0 = 0.f, bb1 = 0.f;
                if (!(MODE == 0 && tauu)) {
                    bb0 = bias_g[cat * HID + n0 + col];
                    bb1 = bias_g[cat * HID + n0 + col + 1];
                }
                float v0 = acc[mt][j][0] + bb0;
                float v1 = acc[mt][j][1] + bb1;
                float v2 = acc[mt][j][2] + bb0;
                float v3 = acc[mt][j][3] + bb1;
                if (MODE == 2) {
                    if (T0) { v0 += T0[col]; v1 += T0[col + 1]; }
                    if (T1) { v2 += T1[col]; v3 += T1[col + 1]; }
                    v0 = v0 / (1.f + expf(-v0));
                    v1 = v1 / (1.f + expf(-v1));
                    v2 = v2 / (1.f + expf(-v2));
                    v3 = v3 / (1.f + expf(-v3));
                }
                if (MODE == 0 && tauu) {
                    float* tb = g_tau + (size_t)cat * NBV * HID + n0 + col;
                    atomicAdd(tb + (size_t)tok0 * HID,     v0);
                    atomicAdd(tb + (size_t)tok0 * HID + 1, v1);
                    atomicAdd(tb + (size_t)tok1 * HID,     v2);
                    atomicAdd(tb + (size_t)tok1 * HID + 1, v3);
                } else if (MODE == 3) {
                    if (tok0 >= 0)
                        *(float2*)(out_ext + (size_t)tok0 * HID + n0 + col) = make_float2(v0, v1);
                    if (tok1 >= 0)
                        *(float2*)(out_ext + (size_t)tok1 * HID + n0 + col) = make_float2(v2, v3);
                } else {
                    __half* oh = (MODE == 0) ? g_x1h : g_h2h;
                    if (tok0 >= 0)
                        *(u32*)(oh + (size_t)tok0 * HID + n0 + col) =
                            hpack(__float2half_rn(v0), __float2half_rn(v1));
                    if (tok1 >= 0)
                        *(u32*)(oh + (size_t)tok1 * HID + n0 + col) =
                            hpack(__float2half_rn(v2), __float2half_rn(v3));
                }
            }
        }
    }
}

// ------------------------------ launch ---------------------------------------
extern "C" void kernel_launch(void* const* d_in, const int* in_sizes, int n_in,
                              void* d_out, int out_size)
{
    const float* actions   = (const float*)d_in[0];
    const int*   timesteps = (const int*)d_in[1];
    const int*   cat_ids   = (const int*)d_in[2];
    const float* W1 = (const float*)d_in[3];
    const float* b1 = (const float*)d_in[4];
    const float* W2 = (const float*)d_in[5];
    const float* b2 = (const float*)d_in[6];
    const float* W3 = (const float*)d_in[7];
    const float* b3 = (const float*)d_in[8];
    float* out = (float*)d_out;
    int nb = in_sizes[1];
    if (nb > NBV) nb = NBV;   // dataset: nb = 128

    cudaFuncSetAttribute((const void*)k_gm<0>,
                         cudaFuncAttributeMaxDynamicSharedMemorySize, SMEM_TOTAL);
    cudaFuncSetAttribute((const void*)k_gm<2>,
                         cudaFuncAttributeMaxDynamicSharedMemorySize, SMEM_TOTAL);
    cudaFuncSetAttribute((const void*)k_gm<3>,
                         cudaFuncAttributeMaxDynamicSharedMemorySize, SMEM_TOTAL);

    // 0: prep (ordering + tauh rows + action convert + T zero)
    k_prep<<<129, 256>>>(cat_ids, timesteps, actions, nb);
    // 1: weight convert+transpose, coalesced
    k_wsplit<<<dim3(32, 49, 8), 256>>>(W1, W2, W3);
    // 2: TAU (K-split x2) + L1, compacted one-wave
    k_gm<0><<<NSM, 256, SMEM_TOTAL>>>(b1, out, nb);
    // 3 (ncu-captured): L2 with T-add + SiLU, compacted one-wave
    k_gm<2><<<NSM, 256, SMEM_TOTAL>>>(b2, out, nb);
    // 4: L3 -> fp32 out, compacted one-wave
    k_gm<3><<<NSM, 256, SMEM_TOTAL>>>(b3, out, nb);
}

// round 12
// speedup vs baseline: 1.0833x; 1.0833x over previous
#include <cuda_runtime.h>
#include <cuda_fp16.h>
#include <math.h>

#define NTOK 4096
#define HID  1024
#define ADIM 64
#define NCAT 8
#define MAXT 40
#define NBV  128
#define NSM  148

typedef unsigned int u32;
typedef unsigned long long u64;

// ---------------- scratch (static device globals; no allocation) -------------
__device__ int g_order[NTOK];
__device__ int g_tile_cat[MAXT];
__device__ int g_tile_row[MAXT];
__device__ int g_cat_base[NCAT];
__device__ int g_cat_count[NCAT];
__device__ int g_num_tiles;

__device__ __align__(16) __half g_ah[NTOK * ADIM];      // actions fp16
__device__ __align__(16) __half g_tauh[NBV * HID];      // tau_emb fp16 (128 rows)
__device__ __align__(16) __half g_x1h[NTOK * HID];      // a_emb fp16
__device__ __align__(16) __half g_h2h[NTOK * HID];      // hidden fp16
__device__ __align__(16) float  g_tau[NCAT * NBV * HID];// T[cat][t][n] fp32

// converted weights: [c][n][k] fp16 (k contiguous, full K rows)
#define W1OFF 0
#define W1SZ  (NCAT * HID * ADIM)
#define W2OFF (W1OFF + W1SZ)
#define W2SZ  (NCAT * HID * 2 * HID)
#define W3OFF (W2OFF + W2SZ)
#define W3SZ  (NCAT * HID * HID)
#define WTOT  (W3OFF + W3SZ)
__device__ __align__(16) __half g_Wh[WTOT];

// ---------------- helpers -----------------------------------------------------
__device__ __forceinline__ u32 smem_u32(const void* p) {
    u32 a;
    asm("{ .reg .u64 t; cvta.to.shared.u64 t, %1; cvt.u32.u64 %0, t; }"
        : "=r"(a) : "l"(p));
    return a;
}
__device__ __forceinline__ u32 hpack(__half a, __half b) {
    return ((u32)__half_as_ushort(b) << 16) | (u32)__half_as_ushort(a);
}
__device__ __forceinline__ u32 swz128(u32 o) { return o ^ ((o >> 3) & 0x70); }

__device__ __forceinline__ void cpasync16(u32 dst, const void* src, u32 srcsz) {
    asm volatile("cp.async.cg.shared.global [%0], [%1], 16, %2;"
                 :: "r"(dst), "l"(src), "r"(srcsz) : "memory");
}
__device__ __forceinline__ void cp_commit() {
    asm volatile("cp.async.commit_group;" ::: "memory");
}
__device__ __forceinline__ void cp_wait2() {
    asm volatile("cp.async.wait_group 2;" ::: "memory");
}
#define LDSM4(r, addr)                                                         \
    asm volatile("ldmatrix.sync.aligned.m8n8.x4.shared.b16 {%0,%1,%2,%3}, [%4];" \
                 : "=r"((r)[0]), "=r"((r)[1]), "=r"((r)[2]), "=r"((r)[3])      \
                 : "r"(addr))
#define MMA(d, a, b)                                                           \
    asm volatile("mma.sync.aligned.m16n8k16.row.col.f32.f16.f16.f32 "          \
                 "{%0,%1,%2,%3},{%4,%5,%6,%7},{%8,%9},{%0,%1,%2,%3};"          \
                 : "+f"((d)[0]), "+f"((d)[1]), "+f"((d)[2]), "+f"((d)[3])      \
                 : "r"((a)[0]), "r"((a)[1]), "r"((a)[2]), "r"((a)[3]),         \
                   "r"((b)[0]), "r"((b)[1]))

// ---------------- prep: ordering (block 0) + tauh + act cvt + tau zero --------
__global__ __launch_bounds__(256)
void k_prep(const int* __restrict__ cat_ids, const int* __restrict__ ts,
            const float* __restrict__ actions, int nb)
{
    int tid = threadIdx.x;
    if (blockIdx.x == 0) {
        __shared__ int thr_cnt[256 * NCAT];
        __shared__ int cat_tot[NCAT];
        __shared__ int cat_base_s[NCAT];
        int loc[NCAT];
        #pragma unroll
        for (int c = 0; c < NCAT; c++) loc[c] = 0;
        int i0 = tid * 16;
        #pragma unroll
        for (int j = 0; j < 16; j++) loc[cat_ids[i0 + j]]++;
        #pragma unroll
        for (int c = 0; c < NCAT; c++) thr_cnt[tid * NCAT + c] = loc[c];
        __syncthreads();
        if (tid < NCAT) {
            int run = 0;
            for (int i = 0; i < 256; i++) {
                int v = thr_cnt[i * NCAT + tid];
                thr_cnt[i * NCAT + tid] = run;
                run += v;
            }
            cat_tot[tid] = run;
        }
        __syncthreads();
        if (tid == 0) {
            int acc = 0, nt = 0;
            for (int c = 0; c < NCAT; c++) {
                g_cat_base[c]  = acc;
                g_cat_count[c] = cat_tot[c];
                cat_base_s[c]  = acc;
                for (int r = 0; r < cat_tot[c]; r += 128) {
                    g_tile_cat[nt] = c;
                    g_tile_row[nt] = acc + r;
                    nt++;
                }
                acc += cat_tot[c];
            }
            g_num_tiles = nt;
        }
        __syncthreads();
        int off[NCAT];
        #pragma unroll
        for (int c = 0; c < NCAT; c++)
            off[c] = cat_base_s[c] + thr_cnt[tid * NCAT + c];
        #pragma unroll
        for (int j = 0; j < 16; j++) {
            int cc = cat_ids[i0 + j];
            g_order[off[cc]++] = i0 + j;
        }
        return;
    }
    int gt = (blockIdx.x - 1) * 256 + tid;
    int stride = (gridDim.x - 1) * 256;
    const float kc = -9.210340371976184f / 512.0f;
    for (int idx = gt; idx < NBV * HID; idx += stride) {
        int t = idx >> 10;
        int j = idx & (HID - 1);
        float v = 0.f;
        if (t < nb) {
            int m = j >> 1;
            float tv = (float)ts[t];
            float ang = tv * expf((float)m * kc);
            v = (j & 1) ? cosf(ang) : sinf(ang);
        }
        g_tauh[idx] = __float2half_rn(v);
    }
    for (int idx = gt; idx < NTOK * ADIM; idx += stride)
        g_ah[idx] = __float2half_rn(actions[idx]);
    for (int idx = gt; idx < NCAT * NBV * HID / 4; idx += stride)
        ((float4*)g_tau)[idx] = make_float4(0.f, 0.f, 0.f, 0.f);
}

// ------- weight convert + transpose, coalesced 128B stores --------------------
__global__ __launch_bounds__(256)
void k_wsplit(const float* __restrict__ W1, const float* __restrict__ W2,
              const float* __restrict__ W3)
{
    __shared__ float s[32][72];
    int ky = blockIdx.y;
    const float* src; size_t woff; int K, kt;
    if (ky < 1)       { src = W1; woff = W1OFF; K = ADIM;    kt = ky; }
    else if (ky < 33) { src = W2; woff = W2OFF; K = 2 * HID; kt = ky - 1; }
    else              { src = W3; woff = W3OFF; K = HID;     kt = ky - 33; }
    int n0 = blockIdx.x * 32, k0 = kt * 64, c = blockIdx.z;
    int tid = threadIdx.x;

    #pragma unroll
    for (int i = 0; i < 2; i++) {
        int idx = tid + i * 256;
        int kr = idx >> 3, n4 = (idx & 7) * 4;
        float4 v = *(const float4*)(src + ((size_t)c * K + k0 + kr) * HID + n0 + n4);
        s[n4 + 0][kr] = v.x;
        s[n4 + 1][kr] = v.y;
        s[n4 + 2][kr] = v.z;
        s[n4 + 3][kr] = v.w;
    }
    __syncthreads();

    int nr = tid >> 3, k8 = (tid & 7) * 8;
    u32 p[4];
    #pragma unroll
    for (int q = 0; q < 4; q++)
        p[q] = hpack(__float2half_rn(s[nr][k8 + 2 * q]),
                     __float2half_rn(s[nr][k8 + 2 * q + 1]));
    size_t di = woff + ((size_t)c * HID + n0 + nr) * (size_t)K + k0 + k8;
    *(uint4*)(g_Wh + di) = make_uint4(p[0], p[1], p[2], p[3]);
}

// ---------------- grouped HMMA GEMM, 512 threads (4 warps/SMSP) ---------------
// CTA tile 128x256, 16 warps in 4x4 grid, warp tile 32x64. K chunks of 64,
// 4-stage cp.async pipeline (wait_group 2, uniform commits).
#define A_OFF 0
#define B_OFF 16384
#define STG   49152
#define NSTG  4
#define SMEM_TOTAL (1024 + NSTG * STG)

template<int MODE>
__global__ __launch_bounds__(512, 1)
void k_gm(const float* __restrict__ bias_g, float* __restrict__ out_ext, int nb)
{
    extern __shared__ char smem[];
    int tid = threadIdx.x, lid = tid & 31, wid = tid >> 5;
    int wm = wid >> 2, wn = wid & 3;           // 4x4 warp grid
    int* tok_s = (int*)smem;
    u32 st0 = smem_u32(smem) + 1024;

    int am = tid >> 3, ac = tid & 7;           // am 0..63
    u32 dst0 = swz128(am * 128 + ac * 16);

    u32 aRow[2], bRow[4];
    #pragma unroll
    for (int mt = 0; mt < 2; mt++)
        aRow[mt] = (wm * 32 + mt * 16 + (lid & 15)) * 128;
    u32 aHs = (lid >> 4) * 16;
    #pragma unroll
    for (int nh = 0; nh < 4; nh++)
        bRow[nh] = (wn * 64 + nh * 16 + (lid & 7) + ((lid >> 4) << 3)) * 128;
    u32 bHs = ((lid >> 3) & 1) * 16;

    int ntl = g_num_tiles;
    int nu = (MODE == 0) ? 64 + 4 * ntl : 4 * ntl;

    for (int u = blockIdx.x; u < nu; u += NSM) {
        __syncthreads();   // prior unit fully retired before tok_s/stage reuse

        int cat, n0, nvalid, row0 = 0, K, ldin, ldw, koff;
        bool tauu = false;
        const __half* inp;
        size_t wb;
        if (MODE == 0 && u < 64) {
            tauu = true;
            int ks = u & 1;
            n0 = ((u >> 1) & 3) * 256;
            cat = u >> 3;
            K = 512; ldin = HID; ldw = 2 * HID; koff = HID + ks * 512;
            inp = g_tauh + ks * 512;
            wb = W2OFF;
            nvalid = 128;
        } else if (MODE == 0) {
            int v = u - 64;
            int tile = v >> 2;
            cat = g_tile_cat[tile]; row0 = g_tile_row[tile];
            n0 = (v & 3) * 256;
            K = ADIM; ldin = ADIM; ldw = ADIM; koff = 0;
            inp = g_ah; wb = W1OFF;
            nvalid = g_cat_base[cat] + g_cat_count[cat] - row0;
            if (nvalid > 128) nvalid = 128;
        } else {
            int tile = u >> 2;
            cat = g_tile_cat[tile]; row0 = g_tile_row[tile];
            n0 = (u & 3) * 256;
            K = HID; ldin = HID; koff = 0;
            if (MODE == 2) { ldw = 2 * HID; inp = g_x1h; wb = W2OFF; }
            else           { ldw = HID;     inp = g_h2h; wb = W3OFF; }
            nvalid = g_cat_base[cat] + g_cat_count[cat] - row0;
            if (nvalid > 128) nvalid = 128;
        }

        if (tid < 128)
            tok_s[tid] = (tid < nvalid) ? (tauu ? tid : g_order[row0 + tid]) : -1;
        __syncthreads();

        // ---- cp.async descriptors ----
        // A: 128 rows x 128B = 1024 x 16B; 512 thr -> 2 each (rows am, am+64)
        const __half* a_src[2];
        u32 a_sz[2];
        #pragma unroll
        for (int i = 0; i < 2; i++) {
            int tok = tok_s[am + 64 * i];
            int t2 = (tok < 0) ? 0 : tok;
            a_src[i] = inp + (size_t)t2 * ldin + ac * 8;
            a_sz[i] = (tok < 0) ? 0u : 16u;
        }
        // B: 256 rows -> 4 each (rows am + 64*i)
        const __half* b_src0 = g_Wh + wb +
                               ((size_t)cat * HID + n0 + am) * (size_t)ldw + koff + ac * 8;
        size_t b_stride = (size_t)64 * ldw;

        float acc[2][8][4];
        #pragma unroll
        for (int i = 0; i < 2; i++)
            #pragma unroll
            for (int j = 0; j < 8; j++)
                #pragma unroll
                for (int q = 0; q < 4; q++) acc[i][j][q] = 0.f;

        int nch = K / 64;

        auto issue = [&](int ch) {
            if (ch < nch) {
                int kg = ch * 64;
                u32 so = st0 + (ch & (NSTG - 1)) * STG;
                #pragma unroll
                for (int i = 0; i < 2; i++)
                    cpasync16(so + A_OFF + dst0 + i * 8192, a_src[i] + kg, a_sz[i]);
                #pragma unroll
                for (int i = 0; i < 4; i++)
                    cpasync16(so + B_OFF + dst0 + i * 8192, b_src0 + i * b_stride + kg, 16);
            }
            cp_commit();   // uniform commits keep wait_group counting valid
        };

        issue(0); issue(1); issue(2);

        for (int c = 0; c < nch; c++) {
            cp_wait2();
            __syncthreads();
            issue(c + 3);

            u32 so = st0 + (c & (NSTG - 1)) * STG;
            #pragma unroll
            for (int s = 0; s < 4; s++) {
                u32 ah[2][4], bh[4][4];
                #pragma unroll
                for (int mt = 0; mt < 2; mt++)
                    LDSM4(ah[mt], so + A_OFF + swz128(aRow[mt] + s * 32 + aHs));
                #pragma unroll
                for (int nh = 0; nh < 4; nh++)
                    LDSM4(bh[nh], so + B_OFF + swz128(bRow[nh] + s * 32 + bHs));
                #pragma unroll
                for (int mt = 0; mt < 2; mt++)
                    #pragma unroll
                    for (int nh = 0; nh < 4; nh++) {
                        MMA(acc[mt][nh * 2 + 0], ah[mt], bh[nh] + 0);
                        MMA(acc[mt][nh * 2 + 1], ah[mt], bh[nh] + 2);
                    }
            }
        }

        // ---- epilogue ----
        int g4 = lid >> 2, t4 = lid & 3;

        #pragma unroll
        for (int mt = 0; mt < 2; mt++) {
            int r0 = wm * 32 + mt * 16 + g4;
            int tok0 = tok_s[r0], tok1 = tok_s[r0 + 8];
            const float *T0 = 0, *T1 = 0;
            if (MODE == 2) {
                if (tok0 >= 0)
                    T0 = g_tau + ((size_t)cat * NBV + (tok0 % nb)) * HID + n0;
                if (tok1 >= 0)
                    T1 = g_tau + ((size_t)cat * NBV + (tok1 % nb)) * HID + n0;
            }
            #pragma unroll
            for (int j = 0; j < 8; j++) {
                int col = wn * 64 + j * 8 + t4 * 2;
                float bb0 = 0.f, bb1 = 0.f;
                if (!(MODE == 0 && tauu)) {
                    bb0 = bias_g[cat * HID + n0 + col];
                    bb1 = bias_g[cat * HID + n0 + col + 1];
                }
                float v0 = acc[mt][j][0] + bb0;
                float v1 = acc[mt][j][1] + bb1;
                float v2 = acc[mt][j][2] + bb0;
                float v3 = acc[mt][j][3] + bb1;
                if (MODE == 2) {
                    if (T0) { v0 += T0[col]; v1 += T0[col + 1]; }
                    if (T1) { v2 += T1[col]; v3 += T1[col + 1]; }
                    v0 = v0 / (1.f + expf(-v0));
                    v1 = v1 / (1.f + expf(-v1));
                    v2 = v2 / (1.f + expf(-v2));
                    v3 = v3 / (1.f + expf(-v3));
                }
                if (MODE == 0 && tauu) {
                    float* tb = g_tau + (size_t)cat * NBV * HID + n0 + col;
                    atomicAdd(tb + (size_t)tok0 * HID,     v0);
                    atomicAdd(tb + (size_t)tok0 * HID + 1, v1);
                    atomicAdd(tb + (size_t)tok1 * HID,     v2);
                    atomicAdd(tb + (size_t)tok1 * HID + 1, v3);
                } else if (MODE == 3) {
                    if (tok0 >= 0)
                        *(float2*)(out_ext + (size_t)tok0 * HID + n0 + col) = make_float2(v0, v1);
                    if (tok1 >= 0)
                        *(float2*)(out_ext + (size_t)tok1 * HID + n0 + col) = make_float2(v2, v3);
                } else {
                    __half* oh = (MODE == 0) ? g_x1h : g_h2h;
                    if (tok0 >= 0)
                        *(u32*)(oh + (size_t)tok0 * HID + n0 + col) =
                            hpack(__float2half_rn(v0), __float2half_rn(v1));
                    if (tok1 >= 0)
                        *(u32*)(oh + (size_t)tok1 * HID + n0 + col) =
                            hpack(__float2half_rn(v2), __float2half_rn(v3));
                }
            }
        }
    }
}

// ------------------------------ launch ---------------------------------------
extern "C" void kernel_launch(void* const* d_in, const int* in_sizes, int n_in,
                              void* d_out, int out_size)
{
    const float* actions   = (const float*)d_in[0];
    const int*   timesteps = (const int*)d_in[1];
    const int*   cat_ids   = (const int*)d_in[2];
    const float* W1 = (const float*)d_in[3];
    const float* b1 = (const float*)d_in[4];
    const float* W2 = (const float*)d_in[5];
    const float* b2 = (const float*)d_in[6];
    const float* W3 = (const float*)d_in[7];
    const float* b3 = (const float*)d_in[8];
    float* out = (float*)d_out;
    int nb = in_sizes[1];
    if (nb > NBV) nb = NBV;   // dataset: nb = 128

    cudaFuncSetAttribute((const void*)k_gm<0>,
                         cudaFuncAttributeMaxDynamicSharedMemorySize, SMEM_TOTAL);
    cudaFuncSetAttribute((const void*)k_gm<2>,
                         cudaFuncAttributeMaxDynamicSharedMemorySize, SMEM_TOTAL);
    cudaFuncSetAttribute((const void*)k_gm<3>,
                         cudaFuncAttributeMaxDynamicSharedMemorySize, SMEM_TOTAL);

    // 0: prep (ordering + tauh rows + action convert + T zero)
    k_prep<<<129, 256>>>(cat_ids, timesteps, actions, nb);
    // 1: weight convert+transpose, coalesced
    k_wsplit<<<dim3(32, 49, 8), 256>>>(W1, W2, W3);
    // 2: TAU (K-split x2) + L1
    k_gm<0><<<NSM, 512, SMEM_TOTAL>>>(b1, out, nb);
    // 3 (ncu-captured): L2 with T-add + SiLU
    k_gm<2><<<NSM, 512, SMEM_TOTAL>>>(b2, out, nb);
    // 4: L3 -> fp32 out
    k_gm<3><<<NSM, 512, SMEM_TOTAL>>>(b3, out, nb);
}

// round 13
// speedup vs baseline: 1.2118x; 1.1186x over previous
#include <cuda_runtime.h>
#include <cuda_fp16.h>
#include <math.h>

#define NTOK 4096
#define HID  1024
#define ADIM 64
#define NCAT 8
#define MAXT 40
#define NBV  128
#define NGR  296

typedef unsigned int u32;
typedef unsigned long long u64;

// ---------------- scratch (static device globals; no allocation) -------------
__device__ int g_order[NTOK];
__device__ int g_tile_cat[MAXT];
__device__ int g_tile_row[MAXT];
__device__ int g_cat_base[NCAT];
__device__ int g_cat_count[NCAT];
__device__ int g_num_tiles;

__device__ __align__(16) __half g_ah[NTOK * ADIM];      // actions fp16
__device__ __align__(16) __half g_tauh[NBV * HID];      // tau_emb fp16 (128 rows)
__device__ __align__(16) __half g_x1h[NTOK * HID];      // a_emb fp16
__device__ __align__(16) __half g_h2h[NTOK * HID];      // hidden fp16
__device__ __align__(16) float  g_tau[NCAT * NBV * HID];// T[cat][t][n] fp32

// converted weights: [c][n][k] fp16 (k contiguous, full K rows)
#define W1OFF 0
#define W1SZ  (NCAT * HID * ADIM)
#define W2OFF (W1OFF + W1SZ)
#define W2SZ  (NCAT * HID * 2 * HID)
#define W3OFF (W2OFF + W2SZ)
#define W3SZ  (NCAT * HID * HID)
#define WTOT  (W3OFF + W3SZ)
__device__ __align__(16) __half g_Wh[WTOT];

// ---------------- helpers -----------------------------------------------------
__device__ __forceinline__ u32 smem_u32(const void* p) {
    u32 a;
    asm("{ .reg .u64 t; cvta.to.shared.u64 t, %1; cvt.u32.u64 %0, t; }"
        : "=r"(a) : "l"(p));
    return a;
}
__device__ __forceinline__ u32 hpack(__half a, __half b) {
    return ((u32)__half_as_ushort(b) << 16) | (u32)__half_as_ushort(a);
}
__device__ __forceinline__ u32 swz128(u32 o) { return o ^ ((o >> 3) & 0x70); }

__device__ __forceinline__ void cpasync16(u32 dst, const void* src, u32 srcsz) {
    asm volatile("cp.async.cg.shared.global [%0], [%1], 16, %2;"
                 :: "r"(dst), "l"(src), "r"(srcsz) : "memory");
}
__device__ __forceinline__ void cp_commit() {
    asm volatile("cp.async.commit_group;" ::: "memory");
}
__device__ __forceinline__ void cp_wait1() {
    asm volatile("cp.async.wait_group 1;" ::: "memory");
}
#define LDSM4(r, addr)                                                         \
    asm volatile("ldmatrix.sync.aligned.m8n8.x4.shared.b16 {%0,%1,%2,%3}, [%4];" \
                 : "=r"((r)[0]), "=r"((r)[1]), "=r"((r)[2]), "=r"((r)[3])      \
                 : "r"(addr))
#define MMA(d, a, b)                                                           \
    asm volatile("mma.sync.aligned.m16n8k16.row.col.f32.f16.f16.f32 "          \
                 "{%0,%1,%2,%3},{%4,%5,%6,%7},{%8,%9},{%0,%1,%2,%3};"          \
                 : "+f"((d)[0]), "+f"((d)[1]), "+f"((d)[2]), "+f"((d)[3])      \
                 : "r"((a)[0]), "r"((a)[1]), "r"((a)[2]), "r"((a)[3]),         \
                   "r"((b)[0]), "r"((b)[1]))

// ---------------- prep: ordering (block 0) + tauh + act cvt + tau zero --------
__global__ __launch_bounds__(256)
void k_prep(const int* __restrict__ cat_ids, const int* __restrict__ ts,
            const float* __restrict__ actions, int nb)
{
    int tid = threadIdx.x;
    if (blockIdx.x == 0) {
        __shared__ int thr_cnt[256 * NCAT];
        __shared__ int cat_tot[NCAT];
        __shared__ int cat_base_s[NCAT];
        int loc[NCAT];
        #pragma unroll
        for (int c = 0; c < NCAT; c++) loc[c] = 0;
        int i0 = tid * 16;
        #pragma unroll
        for (int j = 0; j < 16; j++) loc[cat_ids[i0 + j]]++;
        #pragma unroll
        for (int c = 0; c < NCAT; c++) thr_cnt[tid * NCAT + c] = loc[c];
        __syncthreads();
        if (tid < NCAT) {
            int run = 0;
            for (int i = 0; i < 256; i++) {
                int v = thr_cnt[i * NCAT + tid];
                thr_cnt[i * NCAT + tid] = run;
                run += v;
            }
            cat_tot[tid] = run;
        }
        __syncthreads();
        if (tid == 0) {
            int acc = 0, nt = 0;
            for (int c = 0; c < NCAT; c++) {
                g_cat_base[c]  = acc;
                g_cat_count[c] = cat_tot[c];
                cat_base_s[c]  = acc;
                for (int r = 0; r < cat_tot[c]; r += 128) {
                    g_tile_cat[nt] = c;
                    g_tile_row[nt] = acc + r;
                    nt++;
                }
                acc += cat_tot[c];
            }
            g_num_tiles = nt;
        }
        __syncthreads();
        int off[NCAT];
        #pragma unroll
        for (int c = 0; c < NCAT; c++)
            off[c] = cat_base_s[c] + thr_cnt[tid * NCAT + c];
        #pragma unroll
        for (int j = 0; j < 16; j++) {
            int cc = cat_ids[i0 + j];
            g_order[off[cc]++] = i0 + j;
        }
        return;
    }
    int gt = (blockIdx.x - 1) * 256 + tid;
    int stride = (gridDim.x - 1) * 256;
    const float kc = -9.210340371976184f / 512.0f;
    for (int idx = gt; idx < NBV * HID; idx += stride) {
        int t = idx >> 10;
        int j = idx & (HID - 1);
        float v = 0.f;
        if (t < nb) {
            int m = j >> 1;
            float tv = (float)ts[t];
            float ang = tv * expf((float)m * kc);
            v = (j & 1) ? cosf(ang) : sinf(ang);
        }
        g_tauh[idx] = __float2half_rn(v);
    }
    for (int idx = gt; idx < NTOK * ADIM; idx += stride)
        g_ah[idx] = __float2half_rn(actions[idx]);
    for (int idx = gt; idx < NCAT * NBV * HID / 4; idx += stride)
        ((float4*)g_tau)[idx] = make_float4(0.f, 0.f, 0.f, 0.f);
}

// ------- weight convert + transpose, 64x64 tiles (4x MLP per thread) ----------
__global__ __launch_bounds__(256)
void k_wsplit(const float* __restrict__ W1, const float* __restrict__ W2,
              const float* __restrict__ W3)
{
    __shared__ float s[64][65];
    int ky = blockIdx.y;
    const float* src; size_t woff; int K, kt;
    if (ky < 1)       { src = W1; woff = W1OFF; K = ADIM;    kt = ky; }
    else if (ky < 33) { src = W2; woff = W2OFF; K = 2 * HID; kt = ky - 1; }
    else              { src = W3; woff = W3OFF; K = HID;     kt = ky - 33; }
    int n0 = blockIdx.x * 64, k0 = kt * 64, c = blockIdx.z;
    int tid = threadIdx.x;

    #pragma unroll
    for (int i = 0; i < 4; i++) {
        int idx = tid + i * 256;
        int kr = idx >> 4, n4 = (idx & 15) * 4;
        float4 v = *(const float4*)(src + ((size_t)c * K + k0 + kr) * HID + n0 + n4);
        s[n4 + 0][kr] = v.x;
        s[n4 + 1][kr] = v.y;
        s[n4 + 2][kr] = v.z;
        s[n4 + 3][kr] = v.w;
    }
    __syncthreads();

    #pragma unroll
    for (int i = 0; i < 2; i++) {
        int idx = tid + i * 256;
        int nr = idx >> 3, k8 = (idx & 7) * 8;
        u32 p[4];
        #pragma unroll
        for (int q = 0; q < 4; q++)
            p[q] = hpack(__float2half_rn(s[nr][k8 + 2 * q]),
                         __float2half_rn(s[nr][k8 + 2 * q + 1]));
        size_t di = woff + ((size_t)c * HID + n0 + nr) * (size_t)K + k0 + k8;
        *(uint4*)(g_Wh + di) = make_uint4(p[0], p[1], p[2], p[3]);
    }
}

// ---------------- grouped HMMA GEMM, 128x128 units, 2 CTAs/SM ------------------
// 256 threads, 8 warps (2x4), warp tile 64x32. K chunks of 64, 3-stage
// cp.async pipeline (wait_group 1, uniform commits). grid=296, stride loop.
#define A_OFF 0
#define B_OFF 16384
#define STG   32768
#define NSTG  3
#define SMEM_TOTAL (1024 + NSTG * STG)

template<int MODE>
__global__ __launch_bounds__(256, 2)
void k_gm(const float* __restrict__ bias_g, float* __restrict__ out_ext, int nb)
{
    extern __shared__ char smem[];
    int tid = threadIdx.x, lid = tid & 31, wid = tid >> 5;
    int wm = wid >> 2, wn = wid & 3;           // 2x4 warp grid, warp tile 64x32
    int* tok_s = (int*)smem;
    u32 st0 = smem_u32(smem) + 1024;

    int am = tid >> 3, ac = tid & 7;           // am 0..31
    u32 dst0 = swz128(am * 128 + ac * 16);

    u32 aRow[4], bRow[2];
    #pragma unroll
    for (int mt = 0; mt < 4; mt++)
        aRow[mt] = (wm * 64 + mt * 16 + (lid & 15)) * 128;
    u32 aHs = (lid >> 4) * 16;
    #pragma unroll
    for (int nh = 0; nh < 2; nh++)
        bRow[nh] = (wn * 32 + nh * 16 + (lid & 7) + ((lid >> 4) << 3)) * 128;
    u32 bHs = ((lid >> 3) & 1) * 16;

    int ntl = g_num_tiles;
    int nu = (MODE == 0) ? 128 + 8 * ntl : 8 * ntl;

    for (int u = blockIdx.x; u < nu; u += NGR) {
        __syncthreads();   // prior unit fully retired before tok_s/stage reuse

        int cat, n0, nvalid, row0 = 0, K, ldin, ldw, koff;
        bool tauu = false;
        const __half* inp;
        size_t wb;
        if (MODE == 0 && u < 128) {
            tauu = true;
            int ks = u & 1;
            n0 = ((u >> 1) & 7) * 128;
            cat = u >> 4;
            K = 512; ldin = HID; ldw = 2 * HID; koff = HID + ks * 512;
            inp = g_tauh + ks * 512;
            wb = W2OFF;
            nvalid = 128;
        } else if (MODE == 0) {
            int v = u - 128;
            int tile = v >> 3;
            cat = g_tile_cat[tile]; row0 = g_tile_row[tile];
            n0 = (v & 7) * 128;
            K = ADIM; ldin = ADIM; ldw = ADIM; koff = 0;
            inp = g_ah; wb = W1OFF;
            nvalid = g_cat_base[cat] + g_cat_count[cat] - row0;
            if (nvalid > 128) nvalid = 128;
        } else {
            int tile = u >> 3;
            cat = g_tile_cat[tile]; row0 = g_tile_row[tile];
            n0 = (u & 7) * 128;
            K = HID; ldin = HID; koff = 0;
            if (MODE == 2) { ldw = 2 * HID; inp = g_x1h; wb = W2OFF; }
            else           { ldw = HID;     inp = g_h2h; wb = W3OFF; }
            nvalid = g_cat_base[cat] + g_cat_count[cat] - row0;
            if (nvalid > 128) nvalid = 128;
        }

        if (tid < 128)
            tok_s[tid] = (tid < nvalid) ? (tauu ? tid : g_order[row0 + tid]) : -1;
        __syncthreads();

        // ---- cp.async descriptors ----
        // A: 128 rows -> 4 each (rows am + 32*i)
        const __half* a_src[4];
        u32 a_sz[4];
        #pragma unroll
        for (int i = 0; i < 4; i++) {
            int tok = tok_s[am + 32 * i];
            int t2 = (tok < 0) ? 0 : tok;
            a_src[i] = inp + (size_t)t2 * ldin + ac * 8;
            a_sz[i] = (tok < 0) ? 0u : 16u;
        }
        // B: 128 rows -> 4 each (rows am + 32*i)
        const __half* b_src0 = g_Wh + wb +
                               ((size_t)cat * HID + n0 + am) * (size_t)ldw + koff + ac * 8;
        size_t b_stride = (size_t)32 * ldw;

        float acc[4][4][4];
        #pragma unroll
        for (int i = 0; i < 4; i++)
            #pragma unroll
            for (int j = 0; j < 4; j++)
                #pragma unroll
                for (int q = 0; q < 4; q++) acc[i][j][q] = 0.f;

        int nch = K / 64;

        auto issue = [&](int ch) {
            if (ch < nch) {
                int kg = ch * 64;
                u32 so = st0 + (ch % NSTG) * STG;
                #pragma unroll
                for (int i = 0; i < 4; i++)
                    cpasync16(so + A_OFF + dst0 + i * 4096, a_src[i] + kg, a_sz[i]);
                #pragma unroll
                for (int i = 0; i < 4; i++)
                    cpasync16(so + B_OFF + dst0 + i * 4096, b_src0 + i * b_stride + kg, 16);
            }
            cp_commit();   // uniform commits keep wait_group counting valid
        };

        issue(0); issue(1);

        for (int c = 0; c < nch; c++) {
            cp_wait1();
            __syncthreads();
            issue(c + 2);

            u32 so = st0 + (c % NSTG) * STG;
            #pragma unroll
            for (int s = 0; s < 4; s++) {
                u32 ah[4][4], bh[2][4];
                #pragma unroll
                for (int mt = 0; mt < 4; mt++)
                    LDSM4(ah[mt], so + A_OFF + swz128(aRow[mt] + s * 32 + aHs));
                #pragma unroll
                for (int nh = 0; nh < 2; nh++)
                    LDSM4(bh[nh], so + B_OFF + swz128(bRow[nh] + s * 32 + bHs));
                #pragma unroll
                for (int mt = 0; mt < 4; mt++)
                    #pragma unroll
                    for (int nh = 0; nh < 2; nh++) {
                        MMA(acc[mt][nh * 2 + 0], ah[mt], bh[nh] + 0);
                        MMA(acc[mt][nh * 2 + 1], ah[mt], bh[nh] + 2);
                    }
            }
        }

        // ---- epilogue ----
        int g4 = lid >> 2, t4 = lid & 3;

        #pragma unroll
        for (int mt = 0; mt < 4; mt++) {
            int r0 = wm * 64 + mt * 16 + g4;
            int tok0 = tok_s[r0], tok1 = tok_s[r0 + 8];
            const float *T0 = 0, *T1 = 0;
            if (MODE == 2) {
                if (tok0 >= 0)
                    T0 = g_tau + ((size_t)cat * NBV + (tok0 % nb)) * HID + n0;
                if (tok1 >= 0)
                    T1 = g_tau + ((size_t)cat * NBV + (tok1 % nb)) * HID + n0;
            }
            #pragma unroll
            for (int j = 0; j < 4; j++) {
                int col = wn * 32 + j * 8 + t4 * 2;
                float bb0 = 0.f, bb1 = 0.f;
                if (!(MODE == 0 && tauu)) {
                    bb0 = bias_g[cat * HID + n0 + col];
                    bb1 = bias_g[cat * HID + n0 + col + 1];
                }
                float v0 = acc[mt][j][0] + bb0;
                float v1 = acc[mt][j][1] + bb1;
                float v2 = acc[mt][j][2] + bb0;
                float v3 = acc[mt][j][3] + bb1;
                if (MODE == 2) {
                    if (T0) { v0 += T0[col]; v1 += T0[col + 1]; }
                    if (T1) { v2 += T1[col]; v3 += T1[col + 1]; }
                    v0 = v0 / (1.f + expf(-v0));
                    v1 = v1 / (1.f + expf(-v1));
                    v2 = v2 / (1.f + expf(-v2));
                    v3 = v3 / (1.f + expf(-v3));
                }
                if (MODE == 0 && tauu) {
                    float* tb = g_tau + (size_t)cat * NBV * HID + n0 + col;
                    atomicAdd(tb + (size_t)tok0 * HID,     v0);
                    atomicAdd(tb + (size_t)tok0 * HID + 1, v1);
                    atomicAdd(tb + (size_t)tok1 * HID,     v2);
                    atomicAdd(tb + (size_t)tok1 * HID + 1, v3);
                } else if (MODE == 3) {
                    if (tok0 >= 0)
                        *(float2*)(out_ext + (size_t)tok0 * HID + n0 + col) = make_float2(v0, v1);
                    if (tok1 >= 0)
                        *(float2*)(out_ext + (size_t)tok1 * HID + n0 + col) = make_float2(v2, v3);
                } else {
                    __half* oh = (MODE == 0) ? g_x1h : g_h2h;
                    if (tok0 >= 0)
                        *(u32*)(oh + (size_t)tok0 * HID + n0 + col) =
                            hpack(__float2half_rn(v0), __float2half_rn(v1));
                    if (tok1 >= 0)
                        *(u32*)(oh + (size_t)tok1 * HID + n0 + col) =
                            hpack(__float2half_rn(v2), __float2half_rn(v3));
                }
            }
        }
    }
}

// ------------------------------ launch ---------------------------------------
extern "C" void kernel_launch(void* const* d_in, const int* in_sizes, int n_in,
                              void* d_out, int out_size)
{
    const float* actions   = (const float*)d_in[0];
    const int*   timesteps = (const int*)d_in[1];
    const int*   cat_ids   = (const int*)d_in[2];
    const float* W1 = (const float*)d_in[3];
    const float* b1 = (const float*)d_in[4];
    const float* W2 = (const float*)d_in[5];
    const float* b2 = (const float*)d_in[6];
    const float* W3 = (const float*)d_in[7];
    const float* b3 = (const float*)d_in[8];
    float* out = (float*)d_out;
    int nb = in_sizes[1];
    if (nb > NBV) nb = NBV;   // dataset: nb = 128

    cudaFuncSetAttribute((const void*)k_gm<0>,
                         cudaFuncAttributeMaxDynamicSharedMemorySize, SMEM_TOTAL);
    cudaFuncSetAttribute((const void*)k_gm<2>,
                         cudaFuncAttributeMaxDynamicSharedMemorySize, SMEM_TOTAL);
    cudaFuncSetAttribute((const void*)k_gm<3>,
                         cudaFuncAttributeMaxDynamicSharedMemorySize, SMEM_TOTAL);

    // 0: prep (ordering + tauh rows + action convert + T zero)
    k_prep<<<129, 256>>>(cat_ids, timesteps, actions, nb);
    // 1: weight convert+transpose, 64x64 tiles
    k_wsplit<<<dim3(16, 49, 8), 256>>>(W1, W2, W3);
    // 2: TAU (K-split x2, 128 units) + L1
    k_gm<0><<<NGR, 256, SMEM_TOTAL>>>(b1, out, nb);
    // 3 (ncu-captured): L2 with T-add + SiLU
    k_gm<2><<<NGR, 256, SMEM_TOTAL>>>(b2, out, nb);
    // 4: L3 -> fp32 out
    k_gm<3><<<NGR, 256, SMEM_TOTAL>>>(b3, out, nb);
}